// round 13
// baseline (speedup 1.0000x reference)
#include <cuda_runtime.h>
#include <cuda_fp16.h>
#include <cstdint>

#define BATCH 1024
#define CIN   5
#define NPOS  512
#define DIM   256
#define C4    128
#define MT    64             // positions per CTA
#define AST   264            // act smem row stride (fp16): 132 words -> conflict-free
#define NTHR  256

// smem byte offsets (per-CTA ~70 KB -> 2 CTAs/SM)
#define SM_XS    0                       // 5*64 f32 (reused as flag+reduce scratch late)
#define SM_MK    1280                    // 64 f32
#define SM_BIAS  1536                    // 896 f32
#define SM_ACT   5120                    // single fp16 act buffer: 64*264*2 = 33792
#define SM_WBUF  (SM_ACT + 33792)        // 38912: SINGLE weight chunk buffer
#define WBUF_SZ  32768
#define SM_TOTAL (SM_WBUF + WBUF_SZ)     // 71680 bytes

// per-chunk byte sizes (64 K-cols, fragment-packed fp16: 8B per (ks,c,t))
#define CHB_256  (4 * 256 * 4 * 8)       // 32768
#define CHB_128  (4 * 128 * 4 * 8)       // 16384

// ---------------- device scratch ----------------
__device__ float g_h[(size_t)BATCH * C4 * NPOS];       // 256 MB masked activations
__device__ float g_wtab[C4 * NPOS];
__device__ int   g_cnt[BATCH];                          // per-batch tile completion counters
// fragment-packed fp16 weights per 64-K chunk:
//   record[((kc*4+ks)*C + c)*4 + t] = 8B { w(K0), w(K0+1), w(K0+8), w(K0+9) }, K0 = kc*64+ks*16+t*2
__device__ __align__(16) __half g_W2p[4 * 4 * 256 * 4 * 4];
__device__ __align__(16) __half g_W3p[4 * 4 * 256 * 4 * 4];
__device__ __align__(16) __half g_W4p[4 * 4 * 128 * 4 * 4];

// ---------------- helpers ----------------
__device__ __forceinline__ uint32_t smem_u32(const void* p) {
    uint32_t a;
    asm("{ .reg .u64 t; cvta.to.shared.u64 t, %1; cvt.u32.u64 %0, t; }" : "=r"(a) : "l"(p));
    return a;
}

__device__ __forceinline__ void mma16816h(float* d, const unsigned* a, const unsigned* b) {
    asm volatile(
        "mma.sync.aligned.m16n8k16.row.col.f32.f16.f16.f32 "
        "{%0,%1,%2,%3}, {%4,%5,%6,%7}, {%8,%9}, {%0,%1,%2,%3};"
        : "+f"(d[0]), "+f"(d[1]), "+f"(d[2]), "+f"(d[3])
        : "r"(a[0]), "r"(a[1]), "r"(a[2]), "r"(a[3]), "r"(b[0]), "r"(b[1]));
}

__device__ __forceinline__ unsigned pack_h2(float a, float b) {
    half2 p = __floats2half2_rn(a, b);
    return *(unsigned*)&p;
}

// all 256 threads: async-copy one weight chunk into the single buffer
__device__ __forceinline__ void prefetch_chunk(char* smem, const char* src,
                                               int bytes, int tid)
{
    uint32_t dst = smem_u32(smem + SM_WBUF);
    #pragma unroll 4
    for (int off = tid * 16; off < bytes; off += NTHR * 16)
        asm volatile("cp.async.cg.shared.global [%0], [%1], 16;"
                     :: "r"(dst + off), "l"(src + off));
    asm volatile("cp.async.commit_group;" ::: "memory");
}

// ---------------- prep: fragment-pack fp16 weights, pool table, counter reset ----------------
__device__ __forceinline__ void pack4(__half* base, int rec, const float* w,
                                      int c, int ldw, int K0)
{
    __half v[4];
    #pragma unroll
    for (int u = 0; u < 4; u++)
        v[u] = __float2half_rn(w[c * ldw + K0 + (u >> 1) * 8 + (u & 1)]);
    *(uint2*)&base[rec * 4] = *(uint2*)v;
}

__global__ void prep_kernel(const float* __restrict__ w2, const float* __restrict__ w3,
                            const float* __restrict__ w4, const float* __restrict__ pw)
{
    int i = blockIdx.x * blockDim.x + threadIdx.x;   // 65536 threads

    if (i < BATCH) g_cnt[i] = 0;                     // reset fusion counters every launch

    if (i < 16384) {   // W2 / W3: t, c(256), ks(4), kc(4)
        int t = i & 3, c = (i >> 2) & 255, ks = (i >> 10) & 3, kc = (i >> 12) & 3;
        int K0 = kc * 64 + ks * 16 + t * 2;
        int rec = ((kc * 4 + ks) * 256 + c) * 4 + t;
        pack4(g_W2p, rec, w2, c, DIM, K0);
        pack4(g_W3p, rec, w3, c, DIM, K0);
    }
    if (i < 8192) {    // W4: t, c(128), ks(4), kc(4)
        int t = i & 3, c = (i >> 2) & 127, ks = (i >> 9) & 3, kc = (i >> 11) & 3;
        int K0 = kc * 64 + ks * 16 + t * 2;
        int rec = ((kc * 4 + ks) * 128 + c) * 4 + t;
        pack4(g_W4p, rec, w4, c, DIM, K0);
    }

    // pool weight table (128 x 512)
    int ch = i >> 9, n = i & 511;
    float ratio = (float)n / 511.0f;
    float pos = 20.0f * ratio;
    float fidx = floorf(pos);
    int idx = (int)fidx;
    float frac = pos - fidx;
    int idx2 = idx + 1; if (idx2 > 20) idx2 = 20;
    g_wtab[i] = (1.0f - frac) * pw[ch * 21 + idx] + frac * pw[ch * 21 + idx2];
}

// ---------------- mma layer over 4 single-buffered 64-K chunks, 2 m-tiles/warp ----------------
// Within-CTA load->compute serialization is hidden by the co-resident CTA.
template<int COUT, int NT>
__device__ __forceinline__ void layer_mma(
    char* smem, const __half* __restrict__ wglob,
    const char* __restrict__ wnext, int next_bytes,
    const __half* aH,
    float (*acc0)[4], float (*acc1)[4],
    int tid, int wm, int wn, int g, int t2)
{
    const int CHB = 4 * COUT * 4 * 8;
    const int tq = t2 >> 1;           // lane & 3
    #pragma unroll 1
    for (int kc = 0; kc < 4; kc++) {
        asm volatile("cp.async.wait_group 0;" ::: "memory");
        __syncthreads();               // chunk kc resident & visible

        const uint2* wf = (const uint2*)(smem + SM_WBUF);

        #pragma unroll
        for (int ks = 0; ks < 4; ks++) {
            const int kcol = ks * 16 + t2;
            const int acol = kc * 64 + kcol;
            const int row0 = wm * 32 + g;         // m-tile 0
            const int row1 = row0 + 16;           // m-tile 1
            unsigned ah0[4], ah1[4];
            ah0[0] = *(const unsigned*)&aH[(row0    ) * AST + acol    ];
            ah0[1] = *(const unsigned*)&aH[(row0 + 8) * AST + acol    ];
            ah0[2] = *(const unsigned*)&aH[(row0    ) * AST + acol + 8];
            ah0[3] = *(const unsigned*)&aH[(row0 + 8) * AST + acol + 8];
            ah1[0] = *(const unsigned*)&aH[(row1    ) * AST + acol    ];
            ah1[1] = *(const unsigned*)&aH[(row1 + 8) * AST + acol    ];
            ah1[2] = *(const unsigned*)&aH[(row1    ) * AST + acol + 8];
            ah1[3] = *(const unsigned*)&aH[(row1 + 8) * AST + acol + 8];
            #pragma unroll
            for (int n8 = 0; n8 < NT; n8++) {
                const int c = wn * (NT * 8) + n8 * 8 + g;
                uint2 v = wf[(ks * COUT + c) * 4 + tq];   // LDS.64 B-fragment
                unsigned bh[2] = { v.x, v.y };
                mma16816h(acc0[n8], ah0, bh);
                mma16816h(acc1[n8], ah1, bh);
            }
        }
        __syncthreads();               // all reads of wbuf done before refill
        if (kc < 3)
            prefetch_chunk(smem, (const char*)wglob + (size_t)(kc + 1) * CHB, CHB, tid);
        else if (wnext)
            prefetch_chunk(smem, wnext, next_bytes, tid);   // overlapped with epilogue
    }
}

// ---------------- fused 4-layer MLP (fp16 MMA) + last-arriver sortpool ----------------
__global__ void __launch_bounds__(NTHR, 2)
mlp_kernel(const float* __restrict__ x, const float* __restrict__ mask,
           const float* __restrict__ w1,
           const float* __restrict__ b1, const float* __restrict__ b2,
           const float* __restrict__ b3, const float* __restrict__ b4,
           float* __restrict__ out)
{
    extern __shared__ char smem[];
    const int tid  = threadIdx.x;
    const int lane = tid & 31;
    const int warp = tid >> 5;       // 0..7
    const int wm   = warp & 1;       // 32-row group
    const int wn   = warp >> 1;      // 0..3 n-group
    const int g    = lane >> 2;
    const int t2   = (lane & 3) * 2;
    const int b    = blockIdx.y;
    const int n0   = blockIdx.x * MT;

    // kick off layer-2 chunk 0 immediately (covered by staging + layer-1 scalar work)
    prefetch_chunk(smem, (const char*)g_W2p, CHB_256, tid);

    float* xs    = (float*)(smem + SM_XS);
    float* mkS   = (float*)(smem + SM_MK);
    float* sBias = (float*)(smem + SM_BIAS);
    __half* aH   = (__half*)(smem + SM_ACT);

    // stage x tile, mask, biases
    for (int i = tid; i < CIN * MT; i += NTHR) {
        int k = i / MT, n = i % MT;
        xs[k * MT + n] = x[((size_t)b * CIN + k) * NPOS + n0 + n];
    }
    if (tid < MT) mkS[tid] = mask[(size_t)b * NPOS + n0 + tid] * (1.0f / NPOS);
    for (int i = tid; i < 896; i += NTHR) {
        float v;
        if      (i < 256) v = b1[i];
        else if (i < 512) v = b2[i - 256];
        else if (i < 768) v = b3[i - 512];
        else              v = b4[i - 768];
        sBias[i] = v;
    }
    __syncthreads();

    // ---- layer 1 (scalar f32, K=5): thread -> 2 channels x 32 positions
    {
        const int ch0 = (tid & 127) * 2;
        const int nh  = tid >> 7;            // 0..1
        float wr0[CIN], wr1[CIN];
        #pragma unroll
        for (int k = 0; k < CIN; k++) {
            wr0[k] = __ldg(&w1[ch0 * CIN + k]);
            wr1[k] = __ldg(&w1[(ch0 + 1) * CIN + k]);
        }
        const float bb0 = sBias[ch0], bb1 = sBias[ch0 + 1];
        #pragma unroll 4
        for (int nl = 0; nl < 32; nl++) {
            const int n = nh * 32 + nl;
            float a0 = bb0, a1 = bb1;
            #pragma unroll
            for (int k = 0; k < CIN; k++) {
                float xv = xs[k * MT + n];
                a0 += xv * wr0[k];
                a1 += xv * wr1[k];
            }
            a0 = fmaxf(a0, 0.0f); a1 = fmaxf(a1, 0.0f);
            *(unsigned*)&aH[n * AST + ch0] = pack_h2(a0, a1);
        }
    }
    __syncthreads();

    float acc0[8][4], acc1[8][4];

    // ---- layers 2 and 3 (in-place act update)
    #pragma unroll 1
    for (int L = 0; L < 2; L++) {
        #pragma unroll
        for (int i = 0; i < 8; i++) {
            acc0[i][0]=acc0[i][1]=acc0[i][2]=acc0[i][3]=0.0f;
            acc1[i][0]=acc1[i][1]=acc1[i][2]=acc1[i][3]=0.0f;
        }
        const __half* wg = (L == 0) ? g_W2p : g_W3p;
        const char* wnxt = (L == 0) ? (const char*)g_W3p : (const char*)g_W4p;
        const int nb = (L == 0) ? CHB_256 : CHB_128;
        layer_mma<256, 8>(smem, wg, wnxt, nb, aH, acc0, acc1, tid, wm, wn, g, t2);
        const float* lb = sBias + 256 * (L + 1);
        #pragma unroll
        for (int n8 = 0; n8 < 8; n8++) {
            const int col = wn * 64 + n8 * 8 + t2;
            const float bb0 = lb[col], bb1 = lb[col + 1];
            #pragma unroll
            for (int half_ = 0; half_ < 2; half_++) {
                const int r0 = wm * 32 + g + half_ * 8;
                float v0 = fmaxf(acc0[n8][half_ * 2 + 0] + bb0, 0.0f);
                float v1 = fmaxf(acc0[n8][half_ * 2 + 1] + bb1, 0.0f);
                *(unsigned*)&aH[r0 * AST + col] = pack_h2(v0, v1);
                const int r1 = r0 + 16;
                v0 = fmaxf(acc1[n8][half_ * 2 + 0] + bb0, 0.0f);
                v1 = fmaxf(acc1[n8][half_ * 2 + 1] + bb1, 0.0f);
                *(unsigned*)&aH[r1 * AST + col] = pack_h2(v0, v1);
            }
        }
        __syncthreads();
    }

    // ---- layer 4: A -> transpose buffer (f32, overlays act+wbuf area) -> g_h
    #pragma unroll
    for (int i = 0; i < 4; i++) {
        acc0[i][0]=acc0[i][1]=acc0[i][2]=acc0[i][3]=0.0f;
        acc1[i][0]=acc1[i][1]=acc1[i][2]=acc1[i][3]=0.0f;
    }
    layer_mma<128, 4>(smem, g_W4p, (const char*)0, 0, aH, acc0, acc1, tid, wm, wn, g, t2);

    float* sT = (float*)(smem + SM_ACT);    // [128 c][68 n] f32 = 34816 B (spills 1KB into wbuf, done)
    __syncthreads();                        // all MMA reads of acts/wbuf done
    #pragma unroll
    for (int n8 = 0; n8 < 4; n8++) {
        const int c = wn * 32 + n8 * 8 + t2;
        const float bb0 = sBias[768 + c], bb1 = sBias[768 + c + 1];
        #pragma unroll
        for (int half_ = 0; half_ < 2; half_++) {
            const int n0r = wm * 32 + g + half_ * 8;
            sT[(c    ) * 68 + n0r] = acc0[n8][half_ * 2 + 0] + bb0;
            sT[(c + 1) * 68 + n0r] = acc0[n8][half_ * 2 + 1] + bb1;
            sT[(c    ) * 68 + n0r + 16] = acc1[n8][half_ * 2 + 0] + bb0;
            sT[(c + 1) * 68 + n0r + 16] = acc1[n8][half_ * 2 + 1] + bb1;
        }
    }
    __syncthreads();
    {
        const int c   = tid >> 1;           // 0..127
        const int seg = tid & 1;            // 32-position segment
        float* dst = g_h + (((size_t)b * C4 + c) << 9) + n0 + seg * 32;
        #pragma unroll
        for (int i = 0; i < 8; i++) {
            const int nn = seg * 32 + i * 4;
            float4 v = *(float4*)&sT[c * 68 + nn];
            v.x *= mkS[nn + 0]; v.y *= mkS[nn + 1];
            v.z *= mkS[nn + 2]; v.w *= mkS[nn + 3];
            *(float4*)&dst[i * 4] = v;
        }
    }

    // ================= fused sortpool: 8th-arriving CTA of batch b sorts it =================
    __threadfence();                        // publish our g_h tile
    __syncthreads();                        // all stores issued before the count
    volatile int* flag = (volatile int*)(smem + SM_XS);
    if (tid == 0) {
        int old = atomicAdd(&g_cnt[b], 1);
        *flag = (old == 7) ? 1 : 0;
    }
    __syncthreads();
    if (*flag == 0) return;                 // not the last tile: done
    __threadfence();                        // acquire side of the fence-atomic-fence pattern

    float* sred = (float*)(smem + SM_XS + 64);

    // size feature: mean(mask) * 4
    {
        float s = mask[(size_t)b * NPOS + tid] + mask[(size_t)b * NPOS + tid + 256];
        #pragma unroll
        for (int o = 16; o > 0; o >>= 1) s += __shfl_xor_sync(0xffffffffu, s, o);
        if (lane == 0) sred[warp] = s;
        __syncthreads();
        if (tid == 0) {
            float t = 0.0f;
            #pragma unroll
            for (int i = 0; i < 8; i++) t += sred[i];
            out[b * 129 + 128] = t * (4.0f / NPOS);
        }
    }

    // 8 warps x 16 channels: register bitonic sort (desc, 512) + weighted pool
    for (int c = warp; c < C4; c += 8) {
        const float* row = g_h + (((size_t)b * C4 + c) << 9);
        float v[16];
        #pragma unroll
        for (int r = 0; r < 16; r++) v[r] = row[r * 32 + lane];

        #pragma unroll 1
        for (int k = 2; k <= 512; k <<= 1) {
            #pragma unroll 1
            for (int j = k >> 1; j > 0; j >>= 1) {
                if (j >= 32) {
                    int rj = j >> 5, km = k >> 5;
                    #pragma unroll
                    for (int r = 0; r < 16; r++) {
                        if ((r & rj) == 0) {
                            int r2 = r | rj;
                            bool asc = (r & km) != 0;
                            float a = v[r], bb = v[r2];
                            float lo = fminf(a, bb), hi = fmaxf(a, bb);
                            v[r]  = asc ? lo : hi;
                            v[r2] = asc ? hi : lo;
                        }
                    }
                } else {
                    #pragma unroll
                    for (int r = 0; r < 16; r++) {
                        int i = (r << 5) | lane;
                        bool asc   = (i & k) != 0;
                        bool lower = (lane & j) == 0;
                        float other = __shfl_xor_sync(0xffffffffu, v[r], j);
                        bool takeMin = (lower == asc);
                        v[r] = takeMin ? fminf(v[r], other) : fmaxf(v[r], other);
                    }
                }
            }
        }

        const float* wrow = g_wtab + c * NPOS;
        float s = 0.0f;
        #pragma unroll
        for (int r = 0; r < 16; r++) s += v[r] * wrow[r * 32 + lane];
        #pragma unroll
        for (int o = 16; o > 0; o >>= 1) s += __shfl_xor_sync(0xffffffffu, s, o);
        if (lane == 0) out[b * 129 + c] = s;
    }
}

// ---------------- launch ----------------
extern "C" void kernel_launch(void* const* d_in, const int* in_sizes, int n_in,
                              void* d_out, int out_size)
{
    (void)in_sizes; (void)n_in; (void)out_size;
    const float* x    = (const float*)d_in[0];
    const float* mask = (const float*)d_in[1];
    const float* w1   = (const float*)d_in[2];
    const float* b1   = (const float*)d_in[3];
    const float* w2   = (const float*)d_in[4];
    const float* b2   = (const float*)d_in[5];
    const float* w3   = (const float*)d_in[6];
    const float* b3   = (const float*)d_in[7];
    const float* w4   = (const float*)d_in[8];
    const float* b4   = (const float*)d_in[9];
    const float* pw   = (const float*)d_in[10];
    float* out = (float*)d_out;

    prep_kernel<<<256, 256>>>(w2, w3, w4, pw);

    cudaFuncSetAttribute(mlp_kernel, cudaFuncAttributeMaxDynamicSharedMemorySize, SM_TOTAL);
    dim3 grid(NPOS / MT, BATCH);
    mlp_kernel<<<grid, NTHR, SM_TOTAL>>>(x, mask, w1, b1, b2, b3, b4, out);
}

// round 15
// speedup vs baseline: 1.0495x; 1.0495x over previous
#include <cuda_runtime.h>
#include <cuda_fp16.h>
#include <cstdint>

#define BATCH 1024
#define CIN   5
#define NPOS  512
#define DIM   256
#define C4    128
#define MT    128            // positions per CTA
#define AST   264            // act smem row stride (fp16): 132 words -> conflict-free
#define NTHR  512

// smem byte offsets
#define SM_XS    0                       // 5*128 f32 (reused as flag+reduce scratch late)
#define SM_MK    2560                    // 128 f32
#define SM_BIAS  3072                    // 896 f32
#define SM_ACT   6656                    // single fp16 act buffer (in-place across layers)
#define SM_WBUF  (SM_ACT + 67584)        // 74240: double-buffered weight chunks
#define WBUF_SZ  32768
#define SM_TOTAL (SM_WBUF + 2 * WBUF_SZ) // 139776 bytes

// per-chunk byte sizes (64 K-cols, ks-paired records: 16B per (kspair,c,t))
#define CHB_256  (2 * 256 * 4 * 16)      // 32768
#define CHB_128  (2 * 128 * 4 * 16)      // 16384

// ---------------- device scratch ----------------
__device__ float g_h[(size_t)BATCH * C4 * NPOS];       // 256 MB masked activations
__device__ float g_wtab[C4 * NPOS];
__device__ int   g_cnt[BATCH];                          // per-batch tile completion counters
// ks-paired fp16 weight records per 64-K chunk:
//   16B record[((kc*2+kspair)*C + c)*4 + t] = { frag(ks=2p), frag(ks=2p+1) },
//   each 8B frag = { w(K0), w(K0+1), w(K0+8), w(K0+9) }, K0 = kc*64 + ks*16 + t*2
__device__ __align__(16) __half g_W2p[4 * 2 * 256 * 4 * 8];
__device__ __align__(16) __half g_W3p[4 * 2 * 256 * 4 * 8];
__device__ __align__(16) __half g_W4p[4 * 2 * 128 * 4 * 8];

// ---------------- helpers ----------------
__device__ __forceinline__ uint32_t smem_u32(const void* p) {
    uint32_t a;
    asm("{ .reg .u64 t; cvta.to.shared.u64 t, %1; cvt.u32.u64 %0, t; }" : "=r"(a) : "l"(p));
    return a;
}

__device__ __forceinline__ void mma16816h(float* d, const unsigned* a, const unsigned* b) {
    asm volatile(
        "mma.sync.aligned.m16n8k16.row.col.f32.f16.f16.f32 "
        "{%0,%1,%2,%3}, {%4,%5,%6,%7}, {%8,%9}, {%0,%1,%2,%3};"
        : "+f"(d[0]), "+f"(d[1]), "+f"(d[2]), "+f"(d[3])
        : "r"(a[0]), "r"(a[1]), "r"(a[2]), "r"(a[3]), "r"(b[0]), "r"(b[1]));
}

#define LDM_X4(rr, addr) \
    asm volatile("ldmatrix.sync.aligned.m8n8.x4.shared.b16 {%0,%1,%2,%3}, [%4];" \
        : "=r"((rr)[0]), "=r"((rr)[1]), "=r"((rr)[2]), "=r"((rr)[3]) : "r"(addr))

__device__ __forceinline__ unsigned pack_h2(float a, float b) {
    half2 p = __floats2half2_rn(a, b);
    return *(unsigned*)&p;
}

// all 512 threads: async-copy one weight chunk into ring buffer `buf`
__device__ __forceinline__ void prefetch_chunk(char* smem, int buf, const char* src,
                                               int bytes, int tid)
{
    uint32_t dst = smem_u32(smem + SM_WBUF + buf * WBUF_SZ);
    #pragma unroll 4
    for (int off = tid * 16; off < bytes; off += NTHR * 16)
        asm volatile("cp.async.cg.shared.global [%0], [%1], 16;"
                     :: "r"(dst + off), "l"(src + off));
    asm volatile("cp.async.commit_group;" ::: "memory");
}

// ---------------- prep: ks-paired fp16 weight records, pool table, counter reset ----------------
__device__ __forceinline__ void pack4(__half* base, int rec, const float* w,
                                      int c, int ldw, int K0)
{
    __half v[4];
    #pragma unroll
    for (int u = 0; u < 4; u++)
        v[u] = __float2half_rn(w[c * ldw + K0 + (u >> 1) * 8 + (u & 1)]);
    *(uint2*)&base[rec * 4] = *(uint2*)v;
}

__global__ void prep_kernel(const float* __restrict__ w2, const float* __restrict__ w3,
                            const float* __restrict__ w4, const float* __restrict__ pw)
{
    int i = blockIdx.x * blockDim.x + threadIdx.x;   // 65536 threads

    if (i < BATCH) g_cnt[i] = 0;                     // reset fusion counters every launch

    if (i < 16384) {   // W2 / W3: t, c(256), ks(4), kc(4)
        int t = i & 3, c = (i >> 2) & 255, ks = (i >> 10) & 3, kc = (i >> 12) & 3;
        int K0 = kc * 64 + ks * 16 + t * 2;
        int rec = ((((kc * 2 + (ks >> 1)) * 256 + c) * 4 + t) << 1) + (ks & 1);
        pack4(g_W2p, rec, w2, c, DIM, K0);
        pack4(g_W3p, rec, w3, c, DIM, K0);
    }
    if (i < 8192) {    // W4: t, c(128), ks(4), kc(4)
        int t = i & 3, c = (i >> 2) & 127, ks = (i >> 9) & 3, kc = (i >> 11) & 3;
        int K0 = kc * 64 + ks * 16 + t * 2;
        int rec = ((((kc * 2 + (ks >> 1)) * 128 + c) * 4 + t) << 1) + (ks & 1);
        pack4(g_W4p, rec, w4, c, DIM, K0);
    }

    // pool weight table (128 x 512)
    int ch = i >> 9, n = i & 511;
    float ratio = (float)n / 511.0f;
    float pos = 20.0f * ratio;
    float fidx = floorf(pos);
    int idx = (int)fidx;
    float frac = pos - fidx;
    int idx2 = idx + 1; if (idx2 > 20) idx2 = 20;
    g_wtab[i] = (1.0f - frac) * pw[ch * 21 + idx] + frac * pw[ch * 21 + idx2];
}

// ---------------- mma layer: 4 double-buffered 64-K chunks, ldmatrix A + LDS.128 B ----------------
template<int COUT, int NT>
__device__ __forceinline__ void layer_mma(
    char* smem, const __half* __restrict__ wglob,
    const char* __restrict__ wnext, int next_bytes,
    uint32_t aAddr0, uint32_t aAddr1,   // per-thread ldmatrix base addrs (m-tile 0/1)
    float (*acc0)[4], float (*acc1)[4],
    int tid, int wn, int g, int tq)
{
    const int CHB = 2 * COUT * 4 * 16;
    #pragma unroll 1
    for (int kc = 0; kc < 4; kc++) {
        asm volatile("cp.async.wait_group 0;" ::: "memory");
        __syncthreads();
        if (kc < 3)
            prefetch_chunk(smem, (kc + 1) & 1, (const char*)wglob + (size_t)(kc + 1) * CHB, CHB, tid);
        else if (wnext)
            prefetch_chunk(smem, 0, wnext, next_bytes, tid);

        const uint4* wf = (const uint4*)(smem + SM_WBUF + (kc & 1) * WBUF_SZ);

        #pragma unroll
        for (int kspair = 0; kspair < 2; kspair++) {
            const uint32_t acolE = (uint32_t)(kc * 64 + kspair * 32) * 2;  // bytes
            unsigned aE0[4], aE1[4], aO0[4], aO1[4];
            LDM_X4(aE0, aAddr0 + acolE);
            LDM_X4(aE1, aAddr1 + acolE);
            LDM_X4(aO0, aAddr0 + acolE + 32);
            LDM_X4(aO1, aAddr1 + acolE + 32);
            const uint4* wfp = wf + (kspair * COUT + wn * (NT * 8) + g) * 4 + tq;
            #pragma unroll
            for (int n8 = 0; n8 < NT; n8++) {
                uint4 v = wfp[n8 * 32];            // LDS.128: even-ks + odd-ks B frags
                unsigned bhE[2] = { v.x, v.y };
                unsigned bhO[2] = { v.z, v.w };
                mma16816h(acc0[n8], aE0, bhE);
                mma16816h(acc1[n8], aE1, bhE);
                mma16816h(acc0[n8], aO0, bhO);
                mma16816h(acc1[n8], aO1, bhO);
            }
        }
    }
}

// ---------------- fused 4-layer MLP (fp16 MMA) + last-arriver sortpool ----------------
__global__ void __launch_bounds__(NTHR, 1)
mlp_kernel(const float* __restrict__ x, const float* __restrict__ mask,
           const float* __restrict__ w1,
           const float* __restrict__ b1, const float* __restrict__ b2,
           const float* __restrict__ b3, const float* __restrict__ b4,
           float* __restrict__ out)
{
    extern __shared__ char smem[];
    const int tid  = threadIdx.x;
    const int lane = tid & 31;
    const int warp = tid >> 5;       // 0..15
    const int wm   = warp & 3;       // 32-row group
    const int wn   = warp >> 2;      // 0..3 n-group
    const int g    = lane >> 2;
    const int t2   = (lane & 3) * 2;
    const int tq   = lane & 3;
    const int b    = blockIdx.y;
    const int n0   = blockIdx.x * MT;

    // kick off layer-2 chunk 0 immediately (covered by staging + layer-1 scalar work)
    prefetch_chunk(smem, 0, (const char*)g_W2p, CHB_256, tid);

    float* xs    = (float*)(smem + SM_XS);
    float* mkS   = (float*)(smem + SM_MK);
    float* sBias = (float*)(smem + SM_BIAS);
    __half* aH   = (__half*)(smem + SM_ACT);

    // ldmatrix per-lane base addresses (row + m-column part; acol added per ks)
    uint32_t aAddr0, aAddr1;
    {
        const int m = lane >> 3, r = lane & 7;
        const int row0 = wm * 32 + (m & 1) * 8 + r;
        aAddr0 = smem_u32(aH) + (uint32_t)row0 * (AST * 2) + (uint32_t)(m >> 1) * 16;
        aAddr1 = aAddr0 + 16 * (AST * 2);
    }

    // stage x tile, mask, biases
    for (int i = tid; i < CIN * MT; i += NTHR) {
        int k = i / MT, n = i % MT;
        xs[k * MT + n] = x[((size_t)b * CIN + k) * NPOS + n0 + n];
    }
    if (tid < MT) mkS[tid] = mask[(size_t)b * NPOS + n0 + tid] * (1.0f / NPOS);
    for (int i = tid; i < 896; i += NTHR) {
        float v;
        if      (i < 256) v = b1[i];
        else if (i < 512) v = b2[i - 256];
        else if (i < 768) v = b3[i - 512];
        else              v = b4[i - 768];
        sBias[i] = v;
    }
    __syncthreads();

    // ---- layer 1 (scalar f32, K=5): thread -> 2 channels x 32 positions
    {
        const int ch0 = (tid & 127) * 2;
        const int nh  = tid >> 7;            // 0..3
        float wr0[CIN], wr1[CIN];
        #pragma unroll
        for (int k = 0; k < CIN; k++) {
            wr0[k] = __ldg(&w1[ch0 * CIN + k]);
            wr1[k] = __ldg(&w1[(ch0 + 1) * CIN + k]);
        }
        const float bb0 = sBias[ch0], bb1 = sBias[ch0 + 1];
        #pragma unroll 4
        for (int nl = 0; nl < 32; nl++) {
            const int n = nh * 32 + nl;
            float a0 = bb0, a1 = bb1;
            #pragma unroll
            for (int k = 0; k < CIN; k++) {
                float xv = xs[k * MT + n];
                a0 += xv * wr0[k];
                a1 += xv * wr1[k];
            }
            a0 = fmaxf(a0, 0.0f); a1 = fmaxf(a1, 0.0f);
            *(unsigned*)&aH[n * AST + ch0] = pack_h2(a0, a1);
        }
    }
    __syncthreads();

    float acc0[8][4], acc1[8][4];

    // ---- layers 2 and 3 (in-place act update)
    #pragma unroll 1
    for (int L = 0; L < 2; L++) {
        #pragma unroll
        for (int i = 0; i < 8; i++) {
            acc0[i][0]=acc0[i][1]=acc0[i][2]=acc0[i][3]=0.0f;
            acc1[i][0]=acc1[i][1]=acc1[i][2]=acc1[i][3]=0.0f;
        }
        const __half* wg = (L == 0) ? g_W2p : g_W3p;
        const char* wnxt = (L == 0) ? (const char*)g_W3p : (const char*)g_W4p;
        const int nb = (L == 0) ? CHB_256 : CHB_128;
        layer_mma<256, 8>(smem, wg, wnxt, nb, aAddr0, aAddr1, acc0, acc1, tid, wn, g, tq);
        __syncthreads();                 // all MMA reads done before in-place overwrite
        const float* lb = sBias + 256 * (L + 1);
        #pragma unroll
        for (int n8 = 0; n8 < 8; n8++) {
            const int col = wn * 64 + n8 * 8 + t2;
            const float bb0 = lb[col], bb1 = lb[col + 1];
            #pragma unroll
            for (int half_ = 0; half_ < 2; half_++) {
                const int r0 = wm * 32 + g + half_ * 8;
                float v0 = fmaxf(acc0[n8][half_ * 2 + 0] + bb0, 0.0f);
                float v1 = fmaxf(acc0[n8][half_ * 2 + 1] + bb1, 0.0f);
                *(unsigned*)&aH[r0 * AST + col] = pack_h2(v0, v1);
                const int r1 = r0 + 16;
                v0 = fmaxf(acc1[n8][half_ * 2 + 0] + bb0, 0.0f);
                v1 = fmaxf(acc1[n8][half_ * 2 + 1] + bb1, 0.0f);
                *(unsigned*)&aH[r1 * AST + col] = pack_h2(v0, v1);
            }
        }
        __syncthreads();
    }

    // ---- layer 4: A -> transpose buffer (f32, overlays act area) -> g_h
    #pragma unroll
    for (int i = 0; i < 4; i++) {
        acc0[i][0]=acc0[i][1]=acc0[i][2]=acc0[i][3]=0.0f;
        acc1[i][0]=acc1[i][1]=acc1[i][2]=acc1[i][3]=0.0f;
    }
    layer_mma<128, 4>(smem, g_W4p, (const char*)0, 0, aAddr0, aAddr1, acc0, acc1, tid, wn, g, tq);

    float* sT = (float*)(smem + SM_ACT);    // [128 c][132 n] f32 = 67584 B, overlays act buffer
    __syncthreads();                        // all MMA reads of acts done
    #pragma unroll
    for (int n8 = 0; n8 < 4; n8++) {
        const int c = wn * 32 + n8 * 8 + t2;
        const float bb0 = sBias[768 + c], bb1 = sBias[768 + c + 1];
        #pragma unroll
        for (int half_ = 0; half_ < 2; half_++) {
            const int n0r = wm * 32 + g + half_ * 8;
            sT[(c    ) * 132 + n0r] = acc0[n8][half_ * 2 + 0] + bb0;
            sT[(c + 1) * 132 + n0r] = acc0[n8][half_ * 2 + 1] + bb1;
            sT[(c    ) * 132 + n0r + 16] = acc1[n8][half_ * 2 + 0] + bb0;
            sT[(c + 1) * 132 + n0r + 16] = acc1[n8][half_ * 2 + 1] + bb1;
        }
    }
    __syncthreads();
    {
        const int c   = tid >> 2;           // 0..127
        const int seg = tid & 3;            // 32-position segment
        float* dst = g_h + (((size_t)b * C4 + c) << 9) + n0 + seg * 32;
        #pragma unroll
        for (int i = 0; i < 8; i++) {
            const int nn = seg * 32 + i * 4;
            float4 v = *(float4*)&sT[c * 132 + nn];
            v.x *= mkS[nn + 0]; v.y *= mkS[nn + 1];
            v.z *= mkS[nn + 2]; v.w *= mkS[nn + 3];
            *(float4*)&dst[i * 4] = v;
        }
    }

    // ================= fused sortpool: 4th-arriving CTA of batch b sorts it =================
    __threadfence();                        // publish our g_h tile
    __syncthreads();                        // all stores issued before the count
    volatile int* flag = (volatile int*)(smem + SM_XS);
    if (tid == 0) {
        int old = atomicAdd(&g_cnt[b], 1);
        *flag = (old == 3) ? 1 : 0;
    }
    __syncthreads();
    if (*flag == 0) return;                 // not the last tile: done
    __threadfence();                        // acquire side of the fence-atomic-fence pattern

    float* sred = (float*)(smem + SM_XS + 64);

    // size feature: mean(mask) * 4
    {
        float s = mask[(size_t)b * NPOS + tid];
        #pragma unroll
        for (int o = 16; o > 0; o >>= 1) s += __shfl_xor_sync(0xffffffffu, s, o);
        if (lane == 0) sred[warp] = s;
        __syncthreads();
        if (tid == 0) {
            float t = 0.0f;
            #pragma unroll
            for (int i = 0; i < 16; i++) t += sred[i];
            out[b * 129 + 128] = t * (4.0f / NPOS);
        }
    }

    // 16 warps x 8 channels: register bitonic sort (desc, 512) + weighted pool
    for (int c = warp; c < C4; c += 16) {
        const float* row = g_h + (((size_t)b * C4 + c) << 9);
        float v[16];
        #pragma unroll
        for (int r = 0; r < 16; r++) v[r] = row[r * 32 + lane];

        #pragma unroll 1
        for (int k = 2; k <= 512; k <<= 1) {
            #pragma unroll 1
            for (int j = k >> 1; j > 0; j >>= 1) {
                if (j >= 32) {
                    int rj = j >> 5, km = k >> 5;
                    #pragma unroll
                    for (int r = 0; r < 16; r++) {
                        if ((r & rj) == 0) {
                            int r2 = r | rj;
                            bool asc = (r & km) != 0;
                            float a = v[r], bb = v[r2];
                            float lo = fminf(a, bb), hi = fmaxf(a, bb);
                            v[r]  = asc ? lo : hi;
                            v[r2] = asc ? hi : lo;
                        }
                    }
                } else {
                    #pragma unroll
                    for (int r = 0; r < 16; r++) {
                        int i = (r << 5) | lane;
                        bool asc   = (i & k) != 0;
                        bool lower = (lane & j) == 0;
                        float other = __shfl_xor_sync(0xffffffffu, v[r], j);
                        bool takeMin = (lower == asc);
                        v[r] = takeMin ? fminf(v[r], other) : fmaxf(v[r], other);
                    }
                }
            }
        }

        const float* wrow = g_wtab + c * NPOS;
        float s = 0.0f;
        #pragma unroll
        for (int r = 0; r < 16; r++) s += v[r] * wrow[r * 32 + lane];
        #pragma unroll
        for (int o = 16; o > 0; o >>= 1) s += __shfl_xor_sync(0xffffffffu, s, o);
        if (lane == 0) out[b * 129 + c] = s;
    }
}

// ---------------- launch ----------------
extern "C" void kernel_launch(void* const* d_in, const int* in_sizes, int n_in,
                              void* d_out, int out_size)
{
    (void)in_sizes; (void)n_in; (void)out_size;
    const float* x    = (const float*)d_in[0];
    const float* mask = (const float*)d_in[1];
    const float* w1   = (const float*)d_in[2];
    const float* b1   = (const float*)d_in[3];
    const float* w2   = (const float*)d_in[4];
    const float* b2   = (const float*)d_in[5];
    const float* w3   = (const float*)d_in[6];
    const float* b3   = (const float*)d_in[7];
    const float* w4   = (const float*)d_in[8];
    const float* b4   = (const float*)d_in[9];
    const float* pw   = (const float*)d_in[10];
    float* out = (float*)d_out;

    prep_kernel<<<256, 256>>>(w2, w3, w4, pw);

    cudaFuncSetAttribute(mlp_kernel, cudaFuncAttributeMaxDynamicSharedMemorySize, SM_TOTAL);
    dim3 grid(NPOS / MT, BATCH);
    mlp_kernel<<<grid, NTHR, SM_TOTAL>>>(x, mask, w1, b1, b2, b3, b4, out);
}